// round 15
// baseline (speedup 1.0000x reference)
#include <cuda_runtime.h>
#include <cuda_fp16.h>
#include <cmath>
#include <cstdint>

constexpr int kB = 4, kS = 2048, kD = 1024, kH = 16, kHD = 64, kFF = 4096;
constexpr int kM = kB * kS;
constexpr int kQKV = 3 * kD;

// ---------------- scratch ----------------
__device__ __half g_h1[(size_t)kM * kD];
__device__ __half g_wqkv[(size_t)kD * kQKV];
__device__ float  g_bqkv[kQKV];
__device__ __half g_qkv[(size_t)kM * kQKV];
__device__ __half g_attn[(size_t)kM * kD];
__device__ float  g_x2[(size_t)kM * kD];
__device__ __half g_ff1[(size_t)kM * kFF];
__device__ __half g_wo[(size_t)kD * kD];
__device__ __half g_w1[(size_t)kD * kFF];
__device__ __half g_w2[(size_t)kFF * kD];

// ---------------- helpers ----------------
__device__ __forceinline__ void cp_async16(void* smem, const void* gmem)
{
    unsigned int s = (unsigned int)__cvta_generic_to_shared(smem);
    asm volatile("cp.async.cg.shared.global [%0], [%1], 16;\n" :: "r"(s), "l"(gmem));
}

__device__ __forceinline__ float gelu_exact(float x)
{
    return 0.5f * x * (1.0f + erff(x * 0.70710678118654752f));
}

__device__ __forceinline__ void store_half4(__half* dst, float a, float b, float c, float d)
{
    __half2 h0 = __floats2half2_rn(a, b);
    __half2 h1 = __floats2half2_rn(c, d);
    uint2 u;
    u.x = *reinterpret_cast<unsigned int*>(&h0);
    u.y = *reinterpret_cast<unsigned int*>(&h1);
    *reinterpret_cast<uint2*>(dst) = u;
}

__device__ __forceinline__ unsigned int pack_h2(float a, float b)
{
    __half2 h = __floats2half2_rn(a, b);
    return *reinterpret_cast<unsigned int*>(&h);
}

#define LDM_X4(r0, r1, r2, r3, addr) \
    asm volatile("ldmatrix.sync.aligned.m8n8.x4.shared.b16 {%0,%1,%2,%3}, [%4];" \
        : "=r"(r0), "=r"(r1), "=r"(r2), "=r"(r3) : "r"(addr))

#define LDM_X4_T(r0, r1, r2, r3, addr) \
    asm volatile("ldmatrix.sync.aligned.m8n8.x4.trans.shared.b16 {%0,%1,%2,%3}, [%4];" \
        : "=r"(r0), "=r"(r1), "=r"(r2), "=r"(r3) : "r"(addr))

#define MMA16816(c, a0, a1, a2, a3, b0, b1) \
    asm volatile("mma.sync.aligned.m16n8k16.row.col.f32.f16.f16.f32 " \
        "{%0,%1,%2,%3}, {%4,%5,%6,%7}, {%8,%9}, {%0,%1,%2,%3};" \
        : "+f"(c[0]), "+f"(c[1]), "+f"(c[2]), "+f"(c[3]) \
        : "r"(a0), "r"(a1), "r"(a2), "r"(a3), "r"(b0), "r"(b1))

// ---------------- fp32 -> fp16 weight conversion ----------------
__global__ void tohalf_kernel(const float* __restrict__ src, __half* __restrict__ dst, int n4)
{
    int i = blockIdx.x * blockDim.x + threadIdx.x;
    if (i >= n4) return;
    float4 v = reinterpret_cast<const float4*>(src)[i];
    store_half4(dst + (size_t)i * 4, v.x, v.y, v.z, v.w);
}

// ---------------- weight/bias packing ----------------
__global__ void pack_qkv_kernel(const float* __restrict__ Wq, const float* __restrict__ Wk,
                                const float* __restrict__ Wv, const float* __restrict__ bq,
                                const float* __restrict__ bk, const float* __restrict__ bv)
{
    int idx = blockIdx.x * blockDim.x + threadIdx.x;
    const int total = kD * kQKV;
    if (idx >= total) return;
    int d = idx / kQKV;
    int n = idx % kQKV;
    int sect = n / kD;
    int c = n % kD;
    int h = c / kHD;
    int e = c % kHD;
    const float* W = (sect == 0) ? Wq : (sect == 1) ? Wk : Wv;
    g_wqkv[idx] = __float2half(W[((size_t)h * kD + d) * kHD + e]);
    if (idx < kQKV) {
        const float* bb = (idx < kD) ? bq : (idx < 2 * kD) ? bk : bv;
        g_bqkv[idx] = bb[idx % kD];
    }
}

// ---------------- LayerNorm ----------------
__global__ void ln_kernel(const float* __restrict__ x, const float* __restrict__ g,
                          const float* __restrict__ beta, __half* __restrict__ o)
{
    __shared__ float red[8];
    int row = blockIdx.x;
    int t = threadIdx.x;
    float4 v = reinterpret_cast<const float4*>(x + (size_t)row * kD)[t];
    float s = v.x + v.y + v.z + v.w;
#pragma unroll
    for (int off = 16; off; off >>= 1) s += __shfl_xor_sync(0xffffffffu, s, off);
    if ((t & 31) == 0) red[t >> 5] = s;
    __syncthreads();
    float tot = 0.f;
#pragma unroll
    for (int i = 0; i < 8; i++) tot += red[i];
    float mu = tot * (1.0f / kD);
    __syncthreads();
    float d0 = v.x - mu, d1 = v.y - mu, d2 = v.z - mu, d3 = v.w - mu;
    float s2 = d0 * d0 + d1 * d1 + d2 * d2 + d3 * d3;
#pragma unroll
    for (int off = 16; off; off >>= 1) s2 += __shfl_xor_sync(0xffffffffu, s2, off);
    if ((t & 31) == 0) red[t >> 5] = s2;
    __syncthreads();
    float tot2 = 0.f;
#pragma unroll
    for (int i = 0; i < 8; i++) tot2 += red[i];
    float inv = rsqrtf(tot2 * (1.0f / kD) + 1e-5f);
    float4 gg = reinterpret_cast<const float4*>(g)[t];
    float4 bb = reinterpret_cast<const float4*>(beta)[t];
    store_half4(o + (size_t)row * kD + t * 4,
                d0 * inv * gg.x + bb.x, d1 * inv * gg.y + bb.y,
                d2 * inv * gg.z + bb.z, d3 * inv * gg.w + bb.w);
}

// ---------------- FP16 raw-MMA GEMM: 128x128 block, 64x32 warp, 6-stage, 2 CTAs/SM ----------------
constexpr int GBM = 128, GBN = 128, GBK = 32;
constexpr int NSTAGE = 6;
constexpr int A_LDh = 40;
constexpr int B_LDh = 136;
constexpr int ASZh = GBM * A_LDh;     // 5120
constexpr int BSZh = GBK * B_LDh;     // 4352
constexpr int STAGEh = ASZh + BSZh;   // 9472
constexpr int GEMM_SMEM = NSTAGE * STAGEh * 2;   // 113664 B

__global__ __launch_bounds__(256, 2) void gemm_h(const __half* __restrict__ A,
                                                 const __half* __restrict__ Bm,
                                                 float* __restrict__ C32,
                                                 __half* __restrict__ C16,
                                                 const float* __restrict__ bias,
                                                 const float* __restrict__ res,
                                                 int M, int N, int K, int mode, int out16)
{
    extern __shared__ char smc[];

    const int bm = blockIdx.y * GBM;
    const int bn = blockIdx.x * GBN;
    const int t = threadIdx.x;
    const int warp = t >> 5;
    const int lane = t & 31;
    const int wm = warp >> 2;   // 0..1 -> 64 rows
    const int wn = warp & 3;    // 0..3 -> 32 cols

    float acc[4][4][4];
#pragma unroll
    for (int i = 0; i < 4; i++)
#pragma unroll
        for (int nt = 0; nt < 4; nt++)
#pragma unroll
            for (int e = 0; e < 4; e++) acc[i][nt][e] = 0.f;

    const int KT = K / GBK;

    auto load_tile = [&](int kt, int buf) {
        __half* As = reinterpret_cast<__half*>(smc) + buf * STAGEh;
        __half* Bs = As + ASZh;
        const __half* Ab = A + (size_t)bm * K + (size_t)kt * GBK;
        const __half* Bb = Bm + (size_t)kt * GBK * N + bn;
#pragma unroll
        for (int i = 0; i < 2; i++) {
            int ch = t + i * 256;       // 0..511 (128 rows x 4 chunks)
            int r = ch >> 2;
            int c = (ch & 3) * 8;
            cp_async16(&As[r * A_LDh + c], Ab + (size_t)r * K + c);
        }
#pragma unroll
        for (int i = 0; i < 2; i++) {
            int ch = t + i * 256;       // 0..511 (32 rows x 16 chunks)
            int r = ch >> 4;
            int c = (ch & 15) * 8;
            cp_async16(&Bs[r * B_LDh + c], Bb + (size_t)r * N + c);
        }
        asm volatile("cp.async.commit_group;\n");
    };

    // preload NSTAGE-1 = 5 tiles
    load_tile(0, 0);
    load_tile(1, 1);
    load_tile(2, 2);
    load_tile(3, 3);
    load_tile(4, 4);

    for (int kt = 0; kt < KT; kt++) {
        if (kt + 4 < KT)      { asm volatile("cp.async.wait_group 4;\n" ::: "memory"); }
        else if (kt + 3 < KT) { asm volatile("cp.async.wait_group 3;\n" ::: "memory"); }
        else if (kt + 2 < KT) { asm volatile("cp.async.wait_group 2;\n" ::: "memory"); }
        else if (kt + 1 < KT) { asm volatile("cp.async.wait_group 1;\n" ::: "memory"); }
        else                  { asm volatile("cp.async.wait_group 0;\n" ::: "memory"); }
        __syncthreads();
        if (kt + 5 < KT) load_tile(kt + 5, (kt + 5) % NSTAGE);

        const __half* As = reinterpret_cast<const __half*>(smc) + (kt % NSTAGE) * STAGEh;
        const __half* Bs = As + ASZh;

        uint32_t af[2][4][4];
#pragma unroll
        for (int kk = 0; kk < 2; kk++)
#pragma unroll
            for (int i = 0; i < 4; i++) {
                unsigned int addr = (unsigned int)__cvta_generic_to_shared(
                    &As[(wm * 64 + i * 16 + (lane & 15)) * A_LDh + kk * 16 + (lane >> 4) * 8]);
                LDM_X4(af[kk][i][0], af[kk][i][1], af[kk][i][2], af[kk][i][3], addr);
            }

#pragma unroll
        for (int nt = 0; nt < 4; nt++) {
            uint32_t bb[4];
            unsigned int addr = (unsigned int)__cvta_generic_to_shared(
                &Bs[lane * B_LDh + wn * 32 + nt * 8]);
            LDM_X4_T(bb[0], bb[1], bb[2], bb[3], addr);
#pragma unroll
            for (int i = 0; i < 4; i++) {
                MMA16816(acc[i][nt], af[0][i][0], af[0][i][1], af[0][i][2], af[0][i][3],
                         bb[0], bb[1]);
                MMA16816(acc[i][nt], af[1][i][0], af[1][i][1], af[1][i][2], af[1][i][3],
                         bb[2], bb[3]);
            }
        }
    }

    // ---- register-direct epilogue ----
    const int r0 = bm + wm * 64 + (lane >> 2);
    const int c0 = bn + wn * 32 + ((lane & 3) << 1);
#pragma unroll
    for (int i = 0; i < 4; i++) {
#pragma unroll
        for (int nt = 0; nt < 4; nt++) {
            int col = c0 + nt * 8;
            float2 bb = *reinterpret_cast<const float2*>(bias + col);
#pragma unroll
            for (int hh = 0; hh < 2; hh++) {
                int gr = r0 + i * 16 + hh * 8;
                float v0 = acc[i][nt][hh * 2 + 0] + bb.x;
                float v1 = acc[i][nt][hh * 2 + 1] + bb.y;
                if (mode >= 2) { v0 = gelu_exact(v0); v1 = gelu_exact(v1); }
                if (mode == 1 || mode == 3) {
                    float2 rr = *reinterpret_cast<const float2*>(res + (size_t)gr * N + col);
                    v0 += rr.x; v1 += rr.y;
                }
                if (out16) {
                    __half2 h = __floats2half2_rn(v0, v1);
                    *reinterpret_cast<__half2*>(C16 + (size_t)gr * N + col) = h;
                } else {
                    *reinterpret_cast<float2*>(C32 + (size_t)gr * N + col) = make_float2(v0, v1);
                }
            }
        }
    }
}

// ---------------- FA2-style register-resident flash attention (unchanged) ----------------
constexpr int BQ = 128, BK = 64;
constexpr int QLDh = 72;
constexpr int KVTILE = BK * QLDh;
constexpr int ATT_SMEM = (BQ * QLDh + 4 * KVTILE) * 2;

__global__ __launch_bounds__(256, 2) void attn_kernel(const __half* __restrict__ qkv,
                                                      __half* __restrict__ out)
{
    extern __shared__ char smc[];
    __half* Qs = reinterpret_cast<__half*>(smc);
    __half* Ks = Qs + BQ * QLDh;
    __half* Vs = Ks + 2 * KVTILE;

    const int qb = (int)gridDim.x - 1 - blockIdx.x;
    const int bh = blockIdx.y;
    const int b = bh >> 4, h = bh & 15;
    const int t = threadIdx.x;
    const int w = t >> 5, lane = t & 31;

    const __half* base = qkv + (size_t)b * kS * kQKV + h * kHD;

#pragma unroll
    for (int i = 0; i < 4; i++) {
        int ch = t + i * 256;
        int r = ch >> 3, c = (ch & 7) * 8;
        cp_async16(&Qs[r * QLDh + c], base + (size_t)(qb * BQ + r) * kQKV + c);
    }
    asm volatile("cp.async.commit_group;\n");

    auto load_kv = [&](int jb, int buf) {
        __half* kd = Ks + buf * KVTILE;
        __half* vd = Vs + buf * KVTILE;
#pragma unroll
        for (int i = 0; i < 2; i++) {
            int ch = t + i * 256;
            int r = ch >> 3, c = (ch & 7) * 8;
            const __half* kr = base + (size_t)(jb * BK + r) * kQKV + kD + c;
            cp_async16(&kd[r * QLDh + c], kr);
            cp_async16(&vd[r * QLDh + c], kr + kD);
        }
        asm volatile("cp.async.commit_group;\n");
    };

    const int jmax = 2 * qb + 1;
    load_kv(0, 0);
    load_kv(1, 1);

    const int qr0 = w * 16;
    const int growbase = qb * BQ + qr0;
    const int grmax = growbase + 15;
    const int grow0 = growbase + (lane >> 2);

    uint32_t qa[4][4];
    float oacc[8][4];
#pragma unroll
    for (int nt = 0; nt < 8; nt++)
#pragma unroll
        for (int e = 0; e < 4; e++) oacc[nt][e] = 0.f;
    float m0 = -1e30f, m1 = -1e30f, l0 = 0.f, l1 = 0.f;

    for (int jb = 0; jb <= jmax; jb++) {
        const int buf = jb & 1;
        if (jb >= 1 && jb + 1 <= jmax) load_kv(jb + 1, (jb + 1) & 1);
        if (jb + 1 <= jmax) { asm volatile("cp.async.wait_group 1;\n"); }
        else                { asm volatile("cp.async.wait_group 0;\n"); }
        __syncthreads();

        if (jb == 0) {
#pragma unroll
            for (int kk = 0; kk < 4; kk++) {
                unsigned int addr = (unsigned int)__cvta_generic_to_shared(
                    &Qs[(qr0 + (lane & 15)) * QLDh + kk * 16 + (lane >> 4) * 8]);
                LDM_X4(qa[kk][0], qa[kk][1], qa[kk][2], qa[kk][3], addr);
            }
        }

        if (jb * BK <= grmax) {
            const __half* Kb = Ks + buf * KVTILE;
            const __half* Vb = Vs + buf * KVTILE;

            float sacc[8][4];
#pragma unroll
            for (int nt = 0; nt < 8; nt++) {
#pragma unroll
                for (int e = 0; e < 4; e++) sacc[nt][e] = 0.f;
                const int n0 = nt * 8;
                uint32_t kb[8];
                unsigned int ka0 = (unsigned int)__cvta_generic_to_shared(
                    &Kb[(n0 + (lane & 7)) * QLDh + (lane >> 3) * 8]);
                LDM_X4(kb[0], kb[1], kb[2], kb[3], ka0);
                unsigned int ka1 = (unsigned int)__cvta_generic_to_shared(
                    &Kb[(n0 + (lane & 7)) * QLDh + 32 + (lane >> 3) * 8]);
                LDM_X4(kb[4], kb[5], kb[6], kb[7], ka1);
#pragma unroll
                for (int kk = 0; kk < 4; kk++)
                    MMA16816(sacc[nt], qa[kk][0], qa[kk][1], qa[kk][2], qa[kk][3],
                             kb[2 * kk], kb[2 * kk + 1]);
            }

            const bool domask = (jb * BK + BK - 1 > growbase);
            float mx0 = -1e30f, mx1 = -1e30f;
#pragma unroll
            for (int nt = 0; nt < 8; nt++) {
#pragma unroll
                for (int e = 0; e < 4; e++) {
                    float s = sacc[nt][e] * 0.125f;
                    if (domask) {
                        int gc = jb * BK + nt * 8 + ((lane & 3) << 1) + (e & 1);
                        int gr = grow0 + ((e >= 2) ? 8 : 0);
                        if (gc > gr) s = -1e30f;
                    }
                    sacc[nt][e] = s;
                    if (e < 2) mx0 = fmaxf(mx0, s); else mx1 = fmaxf(mx1, s);
                }
            }
            mx0 = fmaxf(mx0, __shfl_xor_sync(0xffffffffu, mx0, 1));
            mx0 = fmaxf(mx0, __shfl_xor_sync(0xffffffffu, mx0, 2));
            mx1 = fmaxf(mx1, __shfl_xor_sync(0xffffffffu, mx1, 1));
            mx1 = fmaxf(mx1, __shfl_xor_sync(0xffffffffu, mx1, 2));
            float nm0 = fmaxf(m0, mx0), nm1 = fmaxf(m1, mx1);
            float a0 = __expf(m0 - nm0), a1 = __expf(m1 - nm1);
            m0 = nm0; m1 = nm1;

            float sum0 = 0.f, sum1 = 0.f;
            uint32_t pa[4][4];
#pragma unroll
            for (int kk = 0; kk < 4; kk++) {
#pragma unroll
                for (int tt = 0; tt < 2; tt++) {
                    int nt = 2 * kk + tt;
                    float p0 = __expf(sacc[nt][0] - nm0);
                    float p1 = __expf(sacc[nt][1] - nm0);
                    float p2 = __expf(sacc[nt][2] - nm1);
                    float p3 = __expf(sacc[nt][3] - nm1);
                    sum0 += p0 + p1; sum1 += p2 + p3;
                    pa[kk][tt * 2 + 0] = pack_h2(p0, p1);
                    pa[kk][tt * 2 + 1] = pack_h2(p2, p3);
                }
            }
            sum0 += __shfl_xor_sync(0xffffffffu, sum0, 1);
            sum0 += __shfl_xor_sync(0xffffffffu, sum0, 2);
            sum1 += __shfl_xor_sync(0xffffffffu, sum1, 1);
            sum1 += __shfl_xor_sync(0xffffffffu, sum1, 2);
            l0 = l0 * a0 + sum0;
            l1 = l1 * a1 + sum1;

#pragma unroll
            for (int nt = 0; nt < 8; nt++) {
                oacc[nt][0] *= a0; oacc[nt][1] *= a0;
                oacc[nt][2] *= a1; oacc[nt][3] *= a1;
            }

#pragma unroll
            for (int nt = 0; nt < 8; nt++) {
                const int n0 = nt * 8;
                uint32_t vb[8];
                unsigned int va0 = (unsigned int)__cvta_generic_to_shared(
                    &Vb[lane * QLDh + n0]);
                LDM_X4_T(vb[0], vb[1], vb[2], vb[3], va0);
                unsigned int va1 = (unsigned int)__cvta_generic_to_shared(
                    &Vb[(32 + lane) * QLDh + n0]);
                LDM_X4_T(vb[4], vb[5], vb[6], vb[7], va1);
#pragma unroll
                for (int kk = 0; kk < 4; kk++)
                    MMA16816(oacc[nt], pa[kk][0], pa[kk][1], pa[kk][2], pa[kk][3],
                             vb[2 * kk], vb[2 * kk + 1]);
            }
        }
        __syncthreads();
    }

    const float inv0 = 1.0f / l0;
    const float inv1 = 1.0f / l1;
    const int r0 = growbase + (lane >> 2);
    const size_t orow0 = (size_t)(b * kS + r0) * kD + h * kHD;
    const size_t orow1 = orow0 + 8 * kD;
#pragma unroll
    for (int nt = 0; nt < 8; nt++) {
        int c = nt * 8 + ((lane & 3) << 1);
        __half2 v0 = __floats2half2_rn(oacc[nt][0] * inv0, oacc[nt][1] * inv0);
        __half2 v1 = __floats2half2_rn(oacc[nt][2] * inv1, oacc[nt][3] * inv1);
        *reinterpret_cast<__half2*>(out + orow0 + c) = v0;
        *reinterpret_cast<__half2*>(out + orow1 + c) = v1;
    }
}

// ---------------- launch ----------------
extern "C" void kernel_launch(void* const* d_in, const int* in_sizes, int n_in,
                              void* d_out, int out_size)
{
    const float* x    = (const float*)d_in[0];
    const float* Wq   = (const float*)d_in[1];
    const float* bq   = (const float*)d_in[2];
    const float* Wk   = (const float*)d_in[3];
    const float* bk   = (const float*)d_in[4];
    const float* Wv   = (const float*)d_in[5];
    const float* bv   = (const float*)d_in[6];
    const float* Wo   = (const float*)d_in[7];
    const float* bo   = (const float*)d_in[8];
    const float* W1   = (const float*)d_in[9];
    const float* b1   = (const float*)d_in[10];
    const float* W2   = (const float*)d_in[11];
    const float* b2   = (const float*)d_in[12];
    const float* ln1g = (const float*)d_in[13];
    const float* ln1b = (const float*)d_in[14];
    const float* ln2g = (const float*)d_in[15];
    const float* ln2b = (const float*)d_in[16];
    float* out = (float*)d_out;

    __half *h1, *wqkv, *qkv, *attn, *ff1, *wo, *w1, *w2;
    float *bqkv, *x2;
    cudaGetSymbolAddress((void**)&h1,   g_h1);
    cudaGetSymbolAddress((void**)&wqkv, g_wqkv);
    cudaGetSymbolAddress((void**)&bqkv, g_bqkv);
    cudaGetSymbolAddress((void**)&qkv,  g_qkv);
    cudaGetSymbolAddress((void**)&attn, g_attn);
    cudaGetSymbolAddress((void**)&x2,   g_x2);
    cudaGetSymbolAddress((void**)&ff1,  g_ff1);
    cudaGetSymbolAddress((void**)&wo,   g_wo);
    cudaGetSymbolAddress((void**)&w1,   g_w1);
    cudaGetSymbolAddress((void**)&w2,   g_w2);

    cudaFuncSetAttribute(attn_kernel, cudaFuncAttributeMaxDynamicSharedMemorySize, ATT_SMEM);
    cudaFuncSetAttribute(gemm_h, cudaFuncAttributeMaxDynamicSharedMemorySize, GEMM_SMEM);

    tohalf_kernel<<<(kD * kD / 4 + 255) / 256, 256>>>(Wo, wo, kD * kD / 4);
    tohalf_kernel<<<(kD * kFF / 4 + 255) / 256, 256>>>(W1, w1, kD * kFF / 4);
    tohalf_kernel<<<(kFF * kD / 4 + 255) / 256, 256>>>(W2, w2, kFF * kD / 4);
    pack_qkv_kernel<<<(kD * kQKV + 255) / 256, 256>>>(Wq, Wk, Wv, bq, bk, bv);
    ln_kernel<<<kM, 256>>>(x, ln1g, ln1b, h1);
    gemm_h<<<dim3(kQKV / GBN, kM / GBM), 256, GEMM_SMEM>>>(h1, wqkv, nullptr, qkv, bqkv, nullptr,
                                                           kM, kQKV, kD, 0, 1);
    attn_kernel<<<dim3(kS / BQ, kB * kH), 256, ATT_SMEM>>>(qkv, attn);
    gemm_h<<<dim3(kD / GBN, kM / GBM), 256, GEMM_SMEM>>>(attn, wo, x2, nullptr, bo, x,
                                                         kM, kD, kD, 1, 0);
    ln_kernel<<<kM, 256>>>(x2, ln2g, ln2b, h1);
    gemm_h<<<dim3(kFF / GBN, kM / GBM), 256, GEMM_SMEM>>>(h1, w1, nullptr, ff1, b1, nullptr,
                                                          kM, kFF, kD, 2, 1);
    gemm_h<<<dim3(kD / GBN, kM / GBM), 256, GEMM_SMEM>>>(ff1, w2, out, nullptr, b2, x2,
                                                         kM, kD, kFF, 3, 0);
}

// round 16
// speedup vs baseline: 1.0227x; 1.0227x over previous
#include <cuda_runtime.h>
#include <cuda_fp16.h>
#include <cmath>
#include <cstdint>

constexpr int kB = 4, kS = 2048, kD = 1024, kH = 16, kHD = 64, kFF = 4096;
constexpr int kM = kB * kS;
constexpr int kQKV = 3 * kD;

// ---------------- scratch ----------------
__device__ __half g_h1[(size_t)kM * kD];
__device__ __half g_wqkv[(size_t)kD * kQKV];
__device__ float  g_bqkv[kQKV];
__device__ __half g_qkv[(size_t)kM * kQKV];
__device__ __half g_attn[(size_t)kM * kD];
__device__ float  g_x2[(size_t)kM * kD];
__device__ __half g_ff1[(size_t)kM * kFF];
__device__ __half g_wo[(size_t)kD * kD];
__device__ __half g_w1[(size_t)kD * kFF];
__device__ __half g_w2[(size_t)kFF * kD];

// ---------------- helpers ----------------
__device__ __forceinline__ void cp_async16(void* smem, const void* gmem)
{
    unsigned int s = (unsigned int)__cvta_generic_to_shared(smem);
    asm volatile("cp.async.cg.shared.global [%0], [%1], 16;\n" :: "r"(s), "l"(gmem));
}

__device__ __forceinline__ float gelu_exact(float x)
{
    return 0.5f * x * (1.0f + erff(x * 0.70710678118654752f));
}

__device__ __forceinline__ void store_half4(__half* dst, float a, float b, float c, float d)
{
    __half2 h0 = __floats2half2_rn(a, b);
    __half2 h1 = __floats2half2_rn(c, d);
    uint2 u;
    u.x = *reinterpret_cast<unsigned int*>(&h0);
    u.y = *reinterpret_cast<unsigned int*>(&h1);
    *reinterpret_cast<uint2*>(dst) = u;
}

__device__ __forceinline__ unsigned int pack_h2(float a, float b)
{
    __half2 h = __floats2half2_rn(a, b);
    return *reinterpret_cast<unsigned int*>(&h);
}

#define LDM_X4(r0, r1, r2, r3, addr) \
    asm volatile("ldmatrix.sync.aligned.m8n8.x4.shared.b16 {%0,%1,%2,%3}, [%4];" \
        : "=r"(r0), "=r"(r1), "=r"(r2), "=r"(r3) : "r"(addr))

#define LDM_X4_T(r0, r1, r2, r3, addr) \
    asm volatile("ldmatrix.sync.aligned.m8n8.x4.trans.shared.b16 {%0,%1,%2,%3}, [%4];" \
        : "=r"(r0), "=r"(r1), "=r"(r2), "=r"(r3) : "r"(addr))

#define MMA16816(c, a0, a1, a2, a3, b0, b1) \
    asm volatile("mma.sync.aligned.m16n8k16.row.col.f32.f16.f16.f32 " \
        "{%0,%1,%2,%3}, {%4,%5,%6,%7}, {%8,%9}, {%0,%1,%2,%3};" \
        : "+f"(c[0]), "+f"(c[1]), "+f"(c[2]), "+f"(c[3]) \
        : "r"(a0), "r"(a1), "r"(a2), "r"(a3), "r"(b0), "r"(b1))

// ---------------- fp32 -> fp16 weight conversion ----------------
__global__ void tohalf_kernel(const float* __restrict__ src, __half* __restrict__ dst, int n4)
{
    int i = blockIdx.x * blockDim.x + threadIdx.x;
    if (i >= n4) return;
    float4 v = reinterpret_cast<const float4*>(src)[i];
    store_half4(dst + (size_t)i * 4, v.x, v.y, v.z, v.w);
}

// ---------------- weight/bias packing ----------------
__global__ void pack_qkv_kernel(const float* __restrict__ Wq, const float* __restrict__ Wk,
                                const float* __restrict__ Wv, const float* __restrict__ bq,
                                const float* __restrict__ bk, const float* __restrict__ bv)
{
    int idx = blockIdx.x * blockDim.x + threadIdx.x;
    const int total = kD * kQKV;
    if (idx >= total) return;
    int d = idx / kQKV;
    int n = idx % kQKV;
    int sect = n / kD;
    int c = n % kD;
    int h = c / kHD;
    int e = c % kHD;
    const float* W = (sect == 0) ? Wq : (sect == 1) ? Wk : Wv;
    g_wqkv[idx] = __float2half(W[((size_t)h * kD + d) * kHD + e]);
    if (idx < kQKV) {
        const float* bb = (idx < kD) ? bq : (idx < 2 * kD) ? bk : bv;
        g_bqkv[idx] = bb[idx % kD];
    }
}

// ---------------- LayerNorm ----------------
__global__ void ln_kernel(const float* __restrict__ x, const float* __restrict__ g,
                          const float* __restrict__ beta, __half* __restrict__ o)
{
    __shared__ float red[8];
    int row = blockIdx.x;
    int t = threadIdx.x;
    float4 v = reinterpret_cast<const float4*>(x + (size_t)row * kD)[t];
    float s = v.x + v.y + v.z + v.w;
#pragma unroll
    for (int off = 16; off; off >>= 1) s += __shfl_xor_sync(0xffffffffu, s, off);
    if ((t & 31) == 0) red[t >> 5] = s;
    __syncthreads();
    float tot = 0.f;
#pragma unroll
    for (int i = 0; i < 8; i++) tot += red[i];
    float mu = tot * (1.0f / kD);
    __syncthreads();
    float d0 = v.x - mu, d1 = v.y - mu, d2 = v.z - mu, d3 = v.w - mu;
    float s2 = d0 * d0 + d1 * d1 + d2 * d2 + d3 * d3;
#pragma unroll
    for (int off = 16; off; off >>= 1) s2 += __shfl_xor_sync(0xffffffffu, s2, off);
    if ((t & 31) == 0) red[t >> 5] = s2;
    __syncthreads();
    float tot2 = 0.f;
#pragma unroll
    for (int i = 0; i < 8; i++) tot2 += red[i];
    float inv = rsqrtf(tot2 * (1.0f / kD) + 1e-5f);
    float4 gg = reinterpret_cast<const float4*>(g)[t];
    float4 bb = reinterpret_cast<const float4*>(beta)[t];
    store_half4(o + (size_t)row * kD + t * 4,
                d0 * inv * gg.x + bb.x, d1 * inv * gg.y + bb.y,
                d2 * inv * gg.z + bb.z, d3 * inv * gg.w + bb.w);
}

// ---------------- FP16 raw-MMA GEMM: 128x128 block, 64x32 warp, 4-stage, 2 CTAs/SM ----------------
constexpr int GBM = 128, GBN = 128, GBK = 32;
constexpr int NSTAGE = 4;
constexpr int A_LDh = 40;
constexpr int B_LDh = 136;
constexpr int ASZh = GBM * A_LDh;     // 5120
constexpr int BSZh = GBK * B_LDh;     // 4352
constexpr int STAGEh = ASZh + BSZh;   // 9472
constexpr int GEMM_SMEM = NSTAGE * STAGEh * 2;   // 75776 B

__global__ __launch_bounds__(256, 2) void gemm_h(const __half* __restrict__ A,
                                                 const __half* __restrict__ Bm,
                                                 float* __restrict__ C32,
                                                 __half* __restrict__ C16,
                                                 const float* __restrict__ bias,
                                                 const float* __restrict__ res,
                                                 int M, int N, int K, int mode, int out16)
{
    extern __shared__ char smc[];

    const int bm = blockIdx.y * GBM;
    const int bn = blockIdx.x * GBN;
    const int t = threadIdx.x;
    const int warp = t >> 5;
    const int lane = t & 31;
    const int wm = warp >> 2;   // 0..1 -> 64 rows
    const int wn = warp & 3;    // 0..3 -> 32 cols

    float acc[4][4][4];
#pragma unroll
    for (int i = 0; i < 4; i++)
#pragma unroll
        for (int nt = 0; nt < 4; nt++)
#pragma unroll
            for (int e = 0; e < 4; e++) acc[i][nt][e] = 0.f;

    const int KT = K / GBK;

    auto load_tile = [&](int kt, int buf) {
        __half* As = reinterpret_cast<__half*>(smc) + buf * STAGEh;
        __half* Bs = As + ASZh;
        const __half* Ab = A + (size_t)bm * K + (size_t)kt * GBK;
        const __half* Bb = Bm + (size_t)kt * GBK * N + bn;
#pragma unroll
        for (int i = 0; i < 2; i++) {
            int ch = t + i * 256;       // 0..511 (128 rows x 4 chunks)
            int r = ch >> 2;
            int c = (ch & 3) * 8;
            cp_async16(&As[r * A_LDh + c], Ab + (size_t)r * K + c);
        }
#pragma unroll
        for (int i = 0; i < 2; i++) {
            int ch = t + i * 256;       // 0..511 (32 rows x 16 chunks)
            int r = ch >> 4;
            int c = (ch & 15) * 8;
            cp_async16(&Bs[r * B_LDh + c], Bb + (size_t)r * N + c);
        }
        asm volatile("cp.async.commit_group;\n");
    };

    load_tile(0, 0);
    load_tile(1, 1);
    load_tile(2, 2);

    for (int kt = 0; kt < KT; kt++) {
        if (kt + 2 < KT)      { asm volatile("cp.async.wait_group 2;\n" ::: "memory"); }
        else if (kt + 1 < KT) { asm volatile("cp.async.wait_group 1;\n" ::: "memory"); }
        else                  { asm volatile("cp.async.wait_group 0;\n" ::: "memory"); }
        __syncthreads();
        if (kt + 3 < KT) load_tile(kt + 3, (kt + 3) % NSTAGE);

        const __half* As = reinterpret_cast<const __half*>(smc) + (kt % NSTAGE) * STAGEh;
        const __half* Bs = As + ASZh;

        uint32_t af[2][4][4];
#pragma unroll
        for (int kk = 0; kk < 2; kk++)
#pragma unroll
            for (int i = 0; i < 4; i++) {
                unsigned int addr = (unsigned int)__cvta_generic_to_shared(
                    &As[(wm * 64 + i * 16 + (lane & 15)) * A_LDh + kk * 16 + (lane >> 4) * 8]);
                LDM_X4(af[kk][i][0], af[kk][i][1], af[kk][i][2], af[kk][i][3], addr);
            }

#pragma unroll
        for (int nt = 0; nt < 4; nt++) {
            uint32_t bb[4];
            unsigned int addr = (unsigned int)__cvta_generic_to_shared(
                &Bs[lane * B_LDh + wn * 32 + nt * 8]);
            LDM_X4_T(bb[0], bb[1], bb[2], bb[3], addr);
#pragma unroll
            for (int i = 0; i < 4; i++) {
                MMA16816(acc[i][nt], af[0][i][0], af[0][i][1], af[0][i][2], af[0][i][3],
                         bb[0], bb[1]);
                MMA16816(acc[i][nt], af[1][i][0], af[1][i][1], af[1][i][2], af[1][i][3],
                         bb[2], bb[3]);
            }
        }
    }

    // ---- register-direct epilogue ----
    const int r0 = bm + wm * 64 + (lane >> 2);
    const int c0 = bn + wn * 32 + ((lane & 3) << 1);
#pragma unroll
    for (int i = 0; i < 4; i++) {
#pragma unroll
        for (int nt = 0; nt < 4; nt++) {
            int col = c0 + nt * 8;
            float2 bb = *reinterpret_cast<const float2*>(bias + col);
#pragma unroll
            for (int hh = 0; hh < 2; hh++) {
                int gr = r0 + i * 16 + hh * 8;
                float v0 = acc[i][nt][hh * 2 + 0] + bb.x;
                float v1 = acc[i][nt][hh * 2 + 1] + bb.y;
                if (mode >= 2) { v0 = gelu_exact(v0); v1 = gelu_exact(v1); }
                if (mode == 1 || mode == 3) {
                    float2 rr = *reinterpret_cast<const float2*>(res + (size_t)gr * N + col);
                    v0 += rr.x; v1 += rr.y;
                }
                if (out16) {
                    __half2 h = __floats2half2_rn(v0, v1);
                    *reinterpret_cast<__half2*>(C16 + (size_t)gr * N + col) = h;
                } else {
                    *reinterpret_cast<float2*>(C32 + (size_t)gr * N + col) = make_float2(v0, v1);
                }
            }
        }
    }
}

// ---------------- FA2-style register-resident flash attention (unchanged) ----------------
constexpr int BQ = 128, BK = 64;
constexpr int QLDh = 72;
constexpr int KVTILE = BK * QLDh;
constexpr int ATT_SMEM = (BQ * QLDh + 4 * KVTILE) * 2;

__global__ __launch_bounds__(256, 2) void attn_kernel(const __half* __restrict__ qkv,
                                                      __half* __restrict__ out)
{
    extern __shared__ char smc[];
    __half* Qs = reinterpret_cast<__half*>(smc);
    __half* Ks = Qs + BQ * QLDh;
    __half* Vs = Ks + 2 * KVTILE;

    const int qb = (int)gridDim.x - 1 - blockIdx.x;
    const int bh = blockIdx.y;
    const int b = bh >> 4, h = bh & 15;
    const int t = threadIdx.x;
    const int w = t >> 5, lane = t & 31;

    const __half* base = qkv + (size_t)b * kS * kQKV + h * kHD;

#pragma unroll
    for (int i = 0; i < 4; i++) {
        int ch = t + i * 256;
        int r = ch >> 3, c = (ch & 7) * 8;
        cp_async16(&Qs[r * QLDh + c], base + (size_t)(qb * BQ + r) * kQKV + c);
    }
    asm volatile("cp.async.commit_group;\n");

    auto load_kv = [&](int jb, int buf) {
        __half* kd = Ks + buf * KVTILE;
        __half* vd = Vs + buf * KVTILE;
#pragma unroll
        for (int i = 0; i < 2; i++) {
            int ch = t + i * 256;
            int r = ch >> 3, c = (ch & 7) * 8;
            const __half* kr = base + (size_t)(jb * BK + r) * kQKV + kD + c;
            cp_async16(&kd[r * QLDh + c], kr);
            cp_async16(&vd[r * QLDh + c], kr + kD);
        }
        asm volatile("cp.async.commit_group;\n");
    };

    const int jmax = 2 * qb + 1;
    load_kv(0, 0);
    load_kv(1, 1);

    const int qr0 = w * 16;
    const int growbase = qb * BQ + qr0;
    const int grmax = growbase + 15;
    const int grow0 = growbase + (lane >> 2);

    uint32_t qa[4][4];
    float oacc[8][4];
#pragma unroll
    for (int nt = 0; nt < 8; nt++)
#pragma unroll
        for (int e = 0; e < 4; e++) oacc[nt][e] = 0.f;
    float m0 = -1e30f, m1 = -1e30f, l0 = 0.f, l1 = 0.f;

    for (int jb = 0; jb <= jmax; jb++) {
        const int buf = jb & 1;
        if (jb >= 1 && jb + 1 <= jmax) load_kv(jb + 1, (jb + 1) & 1);
        if (jb + 1 <= jmax) { asm volatile("cp.async.wait_group 1;\n"); }
        else                { asm volatile("cp.async.wait_group 0;\n"); }
        __syncthreads();

        if (jb == 0) {
#pragma unroll
            for (int kk = 0; kk < 4; kk++) {
                unsigned int addr = (unsigned int)__cvta_generic_to_shared(
                    &Qs[(qr0 + (lane & 15)) * QLDh + kk * 16 + (lane >> 4) * 8]);
                LDM_X4(qa[kk][0], qa[kk][1], qa[kk][2], qa[kk][3], addr);
            }
        }

        if (jb * BK <= grmax) {
            const __half* Kb = Ks + buf * KVTILE;
            const __half* Vb = Vs + buf * KVTILE;

            float sacc[8][4];
#pragma unroll
            for (int nt = 0; nt < 8; nt++) {
#pragma unroll
                for (int e = 0; e < 4; e++) sacc[nt][e] = 0.f;
                const int n0 = nt * 8;
                uint32_t kb[8];
                unsigned int ka0 = (unsigned int)__cvta_generic_to_shared(
                    &Kb[(n0 + (lane & 7)) * QLDh + (lane >> 3) * 8]);
                LDM_X4(kb[0], kb[1], kb[2], kb[3], ka0);
                unsigned int ka1 = (unsigned int)__cvta_generic_to_shared(
                    &Kb[(n0 + (lane & 7)) * QLDh + 32 + (lane >> 3) * 8]);
                LDM_X4(kb[4], kb[5], kb[6], kb[7], ka1);
#pragma unroll
                for (int kk = 0; kk < 4; kk++)
                    MMA16816(sacc[nt], qa[kk][0], qa[kk][1], qa[kk][2], qa[kk][3],
                             kb[2 * kk], kb[2 * kk + 1]);
            }

            const bool domask = (jb * BK + BK - 1 > growbase);
            float mx0 = -1e30f, mx1 = -1e30f;
#pragma unroll
            for (int nt = 0; nt < 8; nt++) {
#pragma unroll
                for (int e = 0; e < 4; e++) {
                    float s = sacc[nt][e] * 0.125f;
                    if (domask) {
                        int gc = jb * BK + nt * 8 + ((lane & 3) << 1) + (e & 1);
                        int gr = grow0 + ((e >= 2) ? 8 : 0);
                        if (gc > gr) s = -1e30f;
                    }
                    sacc[nt][e] = s;
                    if (e < 2) mx0 = fmaxf(mx0, s); else mx1 = fmaxf(mx1, s);
                }
            }
            mx0 = fmaxf(mx0, __shfl_xor_sync(0xffffffffu, mx0, 1));
            mx0 = fmaxf(mx0, __shfl_xor_sync(0xffffffffu, mx0, 2));
            mx1 = fmaxf(mx1, __shfl_xor_sync(0xffffffffu, mx1, 1));
            mx1 = fmaxf(mx1, __shfl_xor_sync(0xffffffffu, mx1, 2));
            float nm0 = fmaxf(m0, mx0), nm1 = fmaxf(m1, mx1);
            float a0 = __expf(m0 - nm0), a1 = __expf(m1 - nm1);
            m0 = nm0; m1 = nm1;

            float sum0 = 0.f, sum1 = 0.f;
            uint32_t pa[4][4];
#pragma unroll
            for (int kk = 0; kk < 4; kk++) {
#pragma unroll
                for (int tt = 0; tt < 2; tt++) {
                    int nt = 2 * kk + tt;
                    float p0 = __expf(sacc[nt][0] - nm0);
                    float p1 = __expf(sacc[nt][1] - nm0);
                    float p2 = __expf(sacc[nt][2] - nm1);
                    float p3 = __expf(sacc[nt][3] - nm1);
                    sum0 += p0 + p1; sum1 += p2 + p3;
                    pa[kk][tt * 2 + 0] = pack_h2(p0, p1);
                    pa[kk][tt * 2 + 1] = pack_h2(p2, p3);
                }
            }
            sum0 += __shfl_xor_sync(0xffffffffu, sum0, 1);
            sum0 += __shfl_xor_sync(0xffffffffu, sum0, 2);
            sum1 += __shfl_xor_sync(0xffffffffu, sum1, 1);
            sum1 += __shfl_xor_sync(0xffffffffu, sum1, 2);
            l0 = l0 * a0 + sum0;
            l1 = l1 * a1 + sum1;

#pragma unroll
            for (int nt = 0; nt < 8; nt++) {
                oacc[nt][0] *= a0; oacc[nt][1] *= a0;
                oacc[nt][2] *= a1; oacc[nt][3] *= a1;
            }

#pragma unroll
            for (int nt = 0; nt < 8; nt++) {
                const int n0 = nt * 8;
                uint32_t vb[8];
                unsigned int va0 = (unsigned int)__cvta_generic_to_shared(
                    &Vb[lane * QLDh + n0]);
                LDM_X4_T(vb[0], vb[1], vb[2], vb[3], va0);
                unsigned int va1 = (unsigned int)__cvta_generic_to_shared(
                    &Vb[(32 + lane) * QLDh + n0]);
                LDM_X4_T(vb[4], vb[5], vb[6], vb[7], va1);
#pragma unroll
                for (int kk = 0; kk < 4; kk++)
                    MMA16816(oacc[nt], pa[kk][0], pa[kk][1], pa[kk][2], pa[kk][3],
                             vb[2 * kk], vb[2 * kk + 1]);
            }
        }
        __syncthreads();
    }

    const float inv0 = 1.0f / l0;
    const float inv1 = 1.0f / l1;
    const int r0 = growbase + (lane >> 2);
    const size_t orow0 = (size_t)(b * kS + r0) * kD + h * kHD;
    const size_t orow1 = orow0 + 8 * kD;
#pragma unroll
    for (int nt = 0; nt < 8; nt++) {
        int c = nt * 8 + ((lane & 3) << 1);
        __half2 v0 = __floats2half2_rn(oacc[nt][0] * inv0, oacc[nt][1] * inv0);
        __half2 v1 = __floats2half2_rn(oacc[nt][2] * inv1, oacc[nt][3] * inv1);
        *reinterpret_cast<__half2*>(out + orow0 + c) = v0;
        *reinterpret_cast<__half2*>(out + orow1 + c) = v1;
    }
}

// ---------------- launch (fork/join streams for prep overlap) ----------------
extern "C" void kernel_launch(void* const* d_in, const int* in_sizes, int n_in,
                              void* d_out, int out_size)
{
    const float* x    = (const float*)d_in[0];
    const float* Wq   = (const float*)d_in[1];
    const float* bq   = (const float*)d_in[2];
    const float* Wk   = (const float*)d_in[3];
    const float* bk   = (const float*)d_in[4];
    const float* Wv   = (const float*)d_in[5];
    const float* bv   = (const float*)d_in[6];
    const float* Wo   = (const float*)d_in[7];
    const float* bo   = (const float*)d_in[8];
    const float* W1   = (const float*)d_in[9];
    const float* b1   = (const float*)d_in[10];
    const float* W2   = (const float*)d_in[11];
    const float* b2   = (const float*)d_in[12];
    const float* ln1g = (const float*)d_in[13];
    const float* ln1b = (const float*)d_in[14];
    const float* ln2g = (const float*)d_in[15];
    const float* ln2b = (const float*)d_in[16];
    float* out = (float*)d_out;

    __half *h1, *wqkv, *qkv, *attn, *ff1, *wo, *w1, *w2;
    float *bqkv, *x2;
    cudaGetSymbolAddress((void**)&h1,   g_h1);
    cudaGetSymbolAddress((void**)&wqkv, g_wqkv);
    cudaGetSymbolAddress((void**)&bqkv, g_bqkv);
    cudaGetSymbolAddress((void**)&qkv,  g_qkv);
    cudaGetSymbolAddress((void**)&attn, g_attn);
    cudaGetSymbolAddress((void**)&x2,   g_x2);
    cudaGetSymbolAddress((void**)&ff1,  g_ff1);
    cudaGetSymbolAddress((void**)&wo,   g_wo);
    cudaGetSymbolAddress((void**)&w1,   g_w1);
    cudaGetSymbolAddress((void**)&w2,   g_w2);

    cudaFuncSetAttribute(attn_kernel, cudaFuncAttributeMaxDynamicSharedMemorySize, ATT_SMEM);
    cudaFuncSetAttribute(gemm_h, cudaFuncAttributeMaxDynamicSharedMemorySize, GEMM_SMEM);

    // lazily-created side streams + events (host objects only; no device allocation)
    static cudaStream_t sPack = nullptr, sW = nullptr;
    static cudaEvent_t evRoot = nullptr, evPack = nullptr, evWo = nullptr, evW12 = nullptr;
    if (!sPack) {
        cudaStreamCreateWithFlags(&sPack, cudaStreamNonBlocking);
        cudaStreamCreateWithFlags(&sW, cudaStreamNonBlocking);
        cudaEventCreateWithFlags(&evRoot, cudaEventDisableTiming);
        cudaEventCreateWithFlags(&evPack, cudaEventDisableTiming);
        cudaEventCreateWithFlags(&evWo, cudaEventDisableTiming);
        cudaEventCreateWithFlags(&evW12, cudaEventDisableTiming);
    }

    // fork
    cudaEventRecord(evRoot, 0);
    cudaStreamWaitEvent(sPack, evRoot, 0);
    cudaStreamWaitEvent(sW, evRoot, 0);

    // prep on side streams
    pack_qkv_kernel<<<(kD * kQKV + 255) / 256, 256, 0, sPack>>>(Wq, Wk, Wv, bq, bk, bv);
    cudaEventRecord(evPack, sPack);
    tohalf_kernel<<<(kD * kD / 4 + 255) / 256, 256, 0, sW>>>(Wo, wo, kD * kD / 4);
    cudaEventRecord(evWo, sW);
    tohalf_kernel<<<(kD * kFF / 4 + 255) / 256, 256, 0, sW>>>(W1, w1, kD * kFF / 4);
    tohalf_kernel<<<(kFF * kD / 4 + 255) / 256, 256, 0, sW>>>(W2, w2, kFF * kD / 4);
    cudaEventRecord(evW12, sW);

    // main chain on default stream
    ln_kernel<<<kM, 256>>>(x, ln1g, ln1b, h1);
    cudaStreamWaitEvent(0, evPack, 0);      // join: QKV GEMM needs packed weights
    gemm_h<<<dim3(kQKV / GBN, kM / GBM), 256, GEMM_SMEM>>>(h1, wqkv, nullptr, qkv, bqkv, nullptr,
                                                           kM, kQKV, kD, 0, 1);
    attn_kernel<<<dim3(kS / BQ, kB * kH), 256, ATT_SMEM>>>(qkv, attn);
    cudaStreamWaitEvent(0, evWo, 0);        // join: Wo ready
    gemm_h<<<dim3(kD / GBN, kM / GBM), 256, GEMM_SMEM>>>(attn, wo, x2, nullptr, bo, x,
                                                         kM, kD, kD, 1, 0);
    ln_kernel<<<kM, 256>>>(x2, ln2g, ln2b, h1);
    cudaStreamWaitEvent(0, evW12, 0);       // join: W1/W2 ready
    gemm_h<<<dim3(kFF / GBN, kM / GBM), 256, GEMM_SMEM>>>(h1, w1, nullptr, ff1, b1, nullptr,
                                                          kM, kFF, kD, 2, 1);
    gemm_h<<<dim3(kD / GBN, kM / GBM), 256, GEMM_SMEM>>>(ff1, w2, out, nullptr, b2, x2,
                                                         kM, kD, kFF, 3, 0);
}